// round 8
// baseline (speedup 1.0000x reference)
#include <cuda_runtime.h>
#include <cuda_fp16.h>
#include <cstdint>

#define BATCH 32768
#define NF 162
#define KP2 192            // K padded to 3 x 64
#define ACCN 1024
#define XW 2048
#define NB 8
#define MAXT 264

// ---------------- scratch ----------------
__device__ __half g_F[(size_t)2 * BATCH * KP2];      // fp16 features [row][192], zero-padded
__device__ __half g_X[(size_t)BATCH * XW];           // activated accumulator outputs
__device__ __half g_Wt[(size_t)KP2 * ACCN];          // W_acc^T k-major [192][1024], zero-padded
__device__ __half g_W1t[XW * 256];                   // W1^T [k][n]
__device__ float  g_psqt_s[BATCH];
__device__ float  g_psqt_n[BATCH];
__device__ int    g_cnt[NB];
__device__ int    g_perm[NB * BATCH];
__device__ int    g_tilebk[MAXT];
__device__ int    g_tilem0[MAXT];
__device__ int    g_ntiles;

__device__ __forceinline__ uint32_t smem_u32(const void* p) {
    return (uint32_t)__cvta_generic_to_shared(p);
}

// ---------------- setup ----------------
__global__ void __launch_bounds__(256) setup_kernel(const float* __restrict__ Wacc,
                                                    const float* __restrict__ W1) {
    int idx = blockIdx.x * 256 + threadIdx.x;
    if (idx < KP2 * ACCN) {
        int k = idx >> 10, j = idx & 1023;
        float v = (k < NF) ? Wacc[(size_t)j * NF + k] : 0.f;
        g_Wt[idx] = __float2half_rn(v);
    }
    if (idx < XW * 256) {
        int n = idx >> 11, k = idx & 2047;
        g_W1t[(size_t)k * 256 + n] = __float2half_rn(W1[idx]);
    }
    if (idx < NB * BATCH) g_perm[idx] = -1;
    if (idx < NB) g_cnt[idx] = 0;
}

// ---------------- feature pack ----------------
__global__ void __launch_bounds__(256) feat_kernel(const float* __restrict__ stm,
                                                   const float* __restrict__ nstm,
                                                   const float* __restrict__ Wacc) {
    int warp = (blockIdx.x * 256 + threadIdx.x) >> 5;
    int lane = threadIdx.x & 31;
    if (warp >= 2 * BATCH) return;
    const float2* WaccLast = (const float2*)(Wacc + (size_t)ACCN * NF);
    const bool is_stm = (warp < BATCH);
    const float2* src = (const float2*)(is_stm ? stm + (size_t)warp * NF
                                               : nstm + (size_t)(warp - BATCH) * NF);
    __half2* dst = (__half2*)(g_F + (size_t)warp * KP2);

    float cnt = 0.f, ps = 0.f;
    #pragma unroll
    for (int it = 0; it < 3; ++it) {
        int p = lane + it * 32;                      // 96 pairs total (192 halves)
        float x = 0.f, y = 0.f;
        if (p < 81) {
            float2 v = src[p];
            x = v.x; y = v.y;
            float2 w = WaccLast[p];
            ps += x * w.x + y * w.y;
            cnt += x + y;
        }
        dst[p] = __floats2half2_rn(x, y);
    }
    #pragma unroll
    for (int o = 16; o; o >>= 1) {
        cnt += __shfl_xor_sync(0xffffffffu, cnt, o);
        ps  += __shfl_xor_sync(0xffffffffu, ps,  o);
    }
    if (lane == 0) {
        if (is_stm) {
            int pc = (int)(cnt + 0.5f);
            int b  = pc / 20;
            b = (b > NB - 1) ? NB - 1 : b;
            int pos = atomicAdd(&g_cnt[b], 1);
            g_perm[b * BATCH + pos] = warp;
            g_psqt_s[warp] = ps;
        } else {
            g_psqt_n[warp - BATCH] = ps;
        }
    }
}

__global__ void __launch_bounds__(64) prefix_kernel() {
    __shared__ int sbase[NB], snt[NB];
    if (threadIdx.x == 0) {
        int t = 0;
        #pragma unroll
        for (int b = 0; b < NB; ++b) {
            sbase[b] = t;
            int nt = (g_cnt[b] + 127) >> 7;
            snt[b] = nt;
            t += nt;
        }
        g_ntiles = t;
    }
    __syncthreads();
    for (int b = 0; b < NB; ++b)
        for (int i = threadIdx.x; i < snt[b]; i += 64) {
            g_tilebk[sbase[b] + i] = b;
            g_tilem0[sbase[b] + i] = b * BATCH + i * 128;
        }
}

// ---------------- GEMM1: HMMA, 256 thr, 2 blocks/SM, B-resident, BK=64 3-stage ring ----------------
#define BSTR 136    // Bs row stride (128 + 8 pad)
#define A1STR 72    // As row stride (64 + 8 pad)
#define G1_SMEM ((KP2 * BSTR + 3 * 128 * A1STR) * 2)   // 107,520 bytes

__global__ void __launch_bounds__(256, 2) gemm1_kernel(const float* __restrict__ bias) {
    extern __shared__ __half sh[];
    __half* Bs = sh;                        // [192][BSTR]
    __half* As = sh + KP2 * BSTR;           // [3][128][A1STR]
    __shared__ float sbias[128];

    const int tid  = threadIdx.x;
    const int lane = tid & 31, wid = tid >> 5;
    const int wm = wid >> 2, wn = wid & 3;  // 2m x 4n warps; warp tile 64m x 32n
    const int mslot = blockIdx.x;           // 0..35
    const int n0 = blockIdx.y * 128;

    // resident B: 192 rows x 16 chunks of 16B
    for (int idx = tid; idx < KP2 * 16; idx += 256) {
        int k = idx >> 4, c = idx & 15;
        asm volatile("cp.async.cg.shared.global [%0], [%1], 16;\n"
                     :: "r"(smem_u32(Bs + k * BSTR + c * 8)),
                        "l"(g_Wt + (size_t)k * ACCN + n0 + c * 8));
    }
    if (tid < 128) sbias[tid] = bias[n0 + tid];

    const int jmax = (512 - mslot + 35) / 36;
    const int C = 3 * jmax;                 // 64-K chunks

    const int arow = tid >> 1;
    const int ahalf = (tid & 1) * 32;
    auto issueChunk = [&](int c) {
        const int mt = mslot + (c / 3) * 36;
        const int kt = c % 3;
        const __half* src = g_F + (size_t)(mt * 128 + arow) * KP2 + kt * 64 + ahalf;
        uint32_t dst = smem_u32(As + (c % 3) * (128 * A1STR) + arow * A1STR + ahalf);
        #pragma unroll
        for (int i = 0; i < 4; ++i)
            asm volatile("cp.async.cg.shared.global [%0], [%1], 16;\n"
                         :: "r"(dst + i * 16), "l"(src + i * 8));
        asm volatile("cp.async.commit_group;\n");
    };

    issueChunk(0);                          // group 0: B + chunk0
    if (C > 1) issueChunk(1);
    else asm volatile("cp.async.commit_group;\n");

    const int g = lane >> 2, t4 = lane & 3;
    float acc[4][4][4];

    for (int c = 0; c < C; ++c) {
        asm volatile("cp.async.wait_group 1;\n");
        __syncthreads();

        const int kt = c % 3;
        if (kt == 0) {
            #pragma unroll
            for (int i = 0; i < 4; ++i)
                #pragma unroll
                for (int j = 0; j < 4; ++j)
                    #pragma unroll
                    for (int k = 0; k < 4; ++k) acc[i][j][k] = 0.f;
        }

        const __half* Ab = As + (c % 3) * (128 * A1STR);
        #pragma unroll
        for (int kf = 0; kf < 4; ++kf) {
            uint32_t af[4][4], bf[4][2];
            #pragma unroll
            for (int mfp = 0; mfp < 4; ++mfp) {
                const __half* p = Ab + (wm * 64 + mfp * 16 + ((lane >> 3) & 1) * 8 + (lane & 7)) * A1STR
                                     + kf * 16 + (lane >> 4) * 8;
                asm volatile("ldmatrix.sync.aligned.m8n8.x4.shared.b16 {%0,%1,%2,%3}, [%4];\n"
                             : "=r"(af[mfp][0]), "=r"(af[mfp][1]), "=r"(af[mfp][2]), "=r"(af[mfp][3])
                             : "r"(smem_u32(p)));
            }
            #pragma unroll
            for (int ng = 0; ng < 2; ++ng) {
                const __half* p = Bs + (kt * 64 + kf * 16 + ((lane >> 3) & 1) * 8 + (lane & 7)) * BSTR
                                     + wn * 32 + ng * 16 + (lane >> 4) * 8;
                uint32_t r0, r1, r2, r3;
                asm volatile("ldmatrix.sync.aligned.m8n8.x4.trans.shared.b16 {%0,%1,%2,%3}, [%4];\n"
                             : "=r"(r0), "=r"(r1), "=r"(r2), "=r"(r3) : "r"(smem_u32(p)));
                bf[ng * 2 + 0][0] = r0; bf[ng * 2 + 0][1] = r1;
                bf[ng * 2 + 1][0] = r2; bf[ng * 2 + 1][1] = r3;
            }
            #pragma unroll
            for (int mfp = 0; mfp < 4; ++mfp)
                #pragma unroll
                for (int nf = 0; nf < 4; ++nf)
                    asm volatile(
                        "mma.sync.aligned.m16n8k16.row.col.f32.f16.f16.f32 "
                        "{%0,%1,%2,%3}, {%4,%5,%6,%7}, {%8,%9}, {%0,%1,%2,%3};\n"
                        : "+f"(acc[mfp][nf][0]), "+f"(acc[mfp][nf][1]),
                          "+f"(acc[mfp][nf][2]), "+f"(acc[mfp][nf][3])
                        : "r"(af[mfp][0]), "r"(af[mfp][1]), "r"(af[mfp][2]), "r"(af[mfp][3]),
                          "r"(bf[nf][0]), "r"(bf[nf][1]));
        }

        if (c + 2 < C) issueChunk(c + 2);
        else asm volatile("cp.async.commit_group;\n");   // keep group count uniform

        if (kt == 2) {
            // epilogue: bias + clip^2 -> g_X
            const int mt = mslot + (c / 3) * 36;
            #pragma unroll
            for (int mfp = 0; mfp < 4; ++mfp) {
                #pragma unroll
                for (int nf = 0; nf < 4; ++nf) {
                    const int col = n0 + wn * 32 + nf * 8 + 2 * t4;
                    #pragma unroll
                    for (int h = 0; h < 2; ++h) {
                        const int row = mt * 128 + wm * 64 + mfp * 16 + g + h * 8;
                        float v0 = __saturatef(acc[mfp][nf][h * 2 + 0] + sbias[col - n0]);     v0 *= v0;
                        float v1 = __saturatef(acc[mfp][nf][h * 2 + 1] + sbias[col - n0 + 1]); v1 *= v1;
                        const size_t off = (row < BATCH)
                            ? (size_t)row * XW + col
                            : (size_t)(row - BATCH) * XW + ACCN + col;
                        *(__half2*)(g_X + off) = __floats2half2_rn(v0, v1);
                    }
                }
            }
        }
    }
}

// ---------------- GEMM2 (R4 proven): BK=32 double buffer + fused layers 2/3 + PSQT ----------------
#define A2STR 40
__global__ void __launch_bounds__(256) gemm2_kernel(const float* __restrict__ b1,
                                                    const float* __restrict__ W2,
                                                    const float* __restrict__ b2,
                                                    const float* __restrict__ W3,
                                                    const float* __restrict__ b3,
                                                    float* __restrict__ out) {
    __shared__ __align__(16) __half As[2][128 * A2STR];
    __shared__ __align__(16) __half Bs[2][32 * A2STR];
    __shared__ int sperm[128];
    __shared__ float sh1[128 * 33];
    __shared__ float sW2[32 * 32];
    __shared__ float sb2[32];
    __shared__ float sW3[32];
    __shared__ float sb3v;

    if (blockIdx.x >= g_ntiles) return;
    const int bk = g_tilebk[blockIdx.x];
    const int m0 = g_tilem0[blockIdx.x];

    const int tid  = threadIdx.x;
    const int lane = tid & 31, wid = tid >> 5;
    const int wm = wid & 3, wn = wid >> 2;

    if (tid < 128) sperm[tid] = g_perm[m0 + tid];
    for (int i = tid; i < 32 * 32; i += 256) sW2[i] = W2[bk * 32 * 32 + i];
    if (tid < 32) { sb2[tid] = b2[bk * 32 + tid]; sW3[tid] = W3[bk * 32 + tid]; }
    if (tid == 0) sb3v = b3[bk];
    __syncthreads();

    const int arow = tid >> 1;
    const int ac2  = (tid & 1) * 2;
    int rp = sperm[arow]; if (rp < 0) rp = 0;
    const __half* gA = g_X + (size_t)rp * XW + ac2 * 8;
    const int brow = tid >> 2, bc = tid & 3;
    const __half* gB = g_W1t + (size_t)brow * 256 + bk * 32 + bc * 8;

    auto issue = [&](int bufi, int kt) {
        uint32_t sa = smem_u32(&As[bufi][arow * A2STR + ac2 * 8]);
        #pragma unroll
        for (int c = 0; c < 2; ++c)
            asm volatile("cp.async.cg.shared.global [%0], [%1], 16;\n"
                         :: "r"(sa + c * 16), "l"(gA + kt * 32 + c * 8));
        if (tid < 128) {
            uint32_t sb = smem_u32(&Bs[bufi][brow * A2STR + bc * 8]);
            asm volatile("cp.async.cg.shared.global [%0], [%1], 16;\n"
                         :: "r"(sb), "l"(gB + (size_t)kt * 32 * 256));
        }
        asm volatile("cp.async.commit_group;\n");
    };

    float acc[2][2][4];
    #pragma unroll
    for (int i = 0; i < 2; ++i)
        #pragma unroll
        for (int j = 0; j < 2; ++j)
            #pragma unroll
            for (int k = 0; k < 4; ++k) acc[i][j][k] = 0.f;

    issue(0, 0);
    const int KT = XW / 32;
    for (int kt = 0; kt < KT; ++kt) {
        const int bufi = kt & 1;
        if (kt + 1 < KT) {
            issue(bufi ^ 1, kt + 1);
            asm volatile("cp.async.wait_group 1;\n");
        } else {
            asm volatile("cp.async.wait_group 0;\n");
        }
        __syncthreads();

        #pragma unroll
        for (int ks = 0; ks < 2; ++ks) {
            uint32_t af[2][4], bf[2][2];
            #pragma unroll
            for (int mf = 0; mf < 2; ++mf) {
                const __half* p = &As[bufi][(wm * 32 + mf * 16 + ((lane >> 3) & 1) * 8 + (lane & 7)) * A2STR
                                            + ks * 16 + (lane >> 4) * 8];
                asm volatile("ldmatrix.sync.aligned.m8n8.x4.shared.b16 {%0,%1,%2,%3}, [%4];\n"
                             : "=r"(af[mf][0]), "=r"(af[mf][1]), "=r"(af[mf][2]), "=r"(af[mf][3])
                             : "r"(smem_u32(p)));
            }
            {
                const __half* p = &Bs[bufi][(ks * 16 + ((lane >> 3) & 1) * 8 + (lane & 7)) * A2STR
                                            + wn * 16 + (lane >> 4) * 8];
                uint32_t r0, r1, r2, r3;
                asm volatile("ldmatrix.sync.aligned.m8n8.x4.trans.shared.b16 {%0,%1,%2,%3}, [%4];\n"
                             : "=r"(r0), "=r"(r1), "=r"(r2), "=r"(r3) : "r"(smem_u32(p)));
                bf[0][0] = r0; bf[0][1] = r1;
                bf[1][0] = r2; bf[1][1] = r3;
            }
            #pragma unroll
            for (int mf = 0; mf < 2; ++mf)
                #pragma unroll
                for (int nf = 0; nf < 2; ++nf)
                    asm volatile(
                        "mma.sync.aligned.m16n8k16.row.col.f32.f16.f16.f32 "
                        "{%0,%1,%2,%3}, {%4,%5,%6,%7}, {%8,%9}, {%0,%1,%2,%3};\n"
                        : "+f"(acc[mf][nf][0]), "+f"(acc[mf][nf][1]),
                          "+f"(acc[mf][nf][2]), "+f"(acc[mf][nf][3])
                        : "r"(af[mf][0]), "r"(af[mf][1]), "r"(af[mf][2]), "r"(af[mf][3]),
                          "r"(bf[nf][0]), "r"(bf[nf][1]));
        }
        __syncthreads();
    }

    const int g = lane >> 2, t4 = lane & 3;
    #pragma unroll
    for (int mf = 0; mf < 2; ++mf) {
        #pragma unroll
        for (int nf = 0; nf < 2; ++nf) {
            const int col = wn * 16 + nf * 8 + 2 * t4;
            #pragma unroll
            for (int h = 0; h < 2; ++h) {
                const int rl = wm * 32 + mf * 16 + g + h * 8;
                sh1[rl * 33 + col]     = __saturatef(acc[mf][nf][h * 2 + 0] + b1[bk * 32 + col]);
                sh1[rl * 33 + col + 1] = __saturatef(acc[mf][nf][h * 2 + 1] + b1[bk * 32 + col + 1]);
            }
        }
    }
    __syncthreads();

    if (tid < 128) {
        const int r = sperm[tid];
        if (r >= 0) {
            const float* hr = &sh1[tid * 33];
            float o = 0.f;
            #pragma unroll 4
            for (int i = 0; i < 32; ++i) {
                float s = sb2[i];
                const float* wr = &sW2[i * 32];
                #pragma unroll
                for (int j = 0; j < 32; ++j) s += wr[j] * hr[j];
                s = __saturatef(s);
                o += sW3[i] * s;
            }
            o += sb3v + 0.5f * (g_psqt_s[r] - g_psqt_n[r]);
            out[r] = o;
        }
    }
}

// ---------------- launch ----------------
extern "C" void kernel_launch(void* const* d_in, const int* in_sizes, int n_in,
                              void* d_out, int out_size) {
    const float* stm  = (const float*)d_in[0];
    const float* nstm = (const float*)d_in[1];
    const float* Wacc = (const float*)d_in[2];
    const float* bacc = (const float*)d_in[3];
    const float* W1   = (const float*)d_in[4];
    const float* b1   = (const float*)d_in[5];
    const float* W2   = (const float*)d_in[6];
    const float* b2   = (const float*)d_in[7];
    const float* W3   = (const float*)d_in[8];
    const float* b3   = (const float*)d_in[9];
    float* out = (float*)d_out;

    static bool attr_set = false;
    if (!attr_set) {
        cudaFuncSetAttribute(gemm1_kernel, cudaFuncAttributeMaxDynamicSharedMemorySize, G1_SMEM);
        attr_set = true;
    }

    setup_kernel<<<(XW * 256 + 255) / 256, 256>>>(Wacc, W1);
    feat_kernel<<<(2 * BATCH) / 8, 256>>>(stm, nstm, Wacc);
    prefix_kernel<<<1, 64>>>();

    dim3 g1(36, ACCN / 128);
    gemm1_kernel<<<g1, 256, G1_SMEM>>>(bacc);

    gemm2_kernel<<<MAXT, 256>>>(b1, W2, b2, W3, b3, out);
}

// round 9
// speedup vs baseline: 1.1076x; 1.1076x over previous
#include <cuda_runtime.h>
#include <cuda_fp16.h>
#include <cstdint>

#define BATCH 32768
#define NF 162
#define KPAD 176
#define ACCN 1024
#define XW 2048
#define NB 8
#define MAXT 264

// ---------------- scratch ----------------
__device__ __half g_F[(size_t)2 * BATCH * KPAD];
__device__ __half g_X[(size_t)BATCH * XW];
__device__ __half g_Wt[(size_t)KPAD * ACCN];         // W_acc^T k-major, zero-padded
__device__ __half g_W1t[XW * 256];                   // W1^T [k][n]
__device__ float  g_psqt_s[BATCH];
__device__ float  g_psqt_n[BATCH];
__device__ int    g_cnt[NB];                         // zero at load; re-zeroed by prefix each run
__device__ int    g_perm[NB * BATCH];
__device__ int    g_tilebk[MAXT];
__device__ int    g_tilem0[MAXT];
__device__ int    g_ntiles;

__device__ __forceinline__ uint32_t smem_u32(const void* p) {
    return (uint32_t)__cvta_generic_to_shared(p);
}

// ---------------- prep: weight packing blocks + feature blocks in one launch ----------------
#define SETUP_BLOCKS 2048
__global__ void __launch_bounds__(256) prep_kernel(const float* __restrict__ stm,
                                                   const float* __restrict__ nstm,
                                                   const float* __restrict__ Wacc,
                                                   const float* __restrict__ W1) {
    if (blockIdx.x < SETUP_BLOCKS) {
        int idx = blockIdx.x * 256 + threadIdx.x;
        if (idx < KPAD * ACCN) {
            int k = idx >> 10, j = idx & 1023;
            float v = (k < NF) ? Wacc[(size_t)j * NF + k] : 0.f;
            g_Wt[idx] = __float2half_rn(v);
        }
        if (idx < XW * 256) {
            int n = idx >> 11, k = idx & 2047;
            g_W1t[(size_t)k * 256 + n] = __float2half_rn(W1[idx]);
        }
        return;
    }
    // feature part: one warp per (side,row)
    int warp = ((blockIdx.x - SETUP_BLOCKS) * 256 + threadIdx.x) >> 5;
    int lane = threadIdx.x & 31;
    if (warp >= 2 * BATCH) return;
    const float2* WaccLast = (const float2*)(Wacc + (size_t)ACCN * NF);
    const bool is_stm = (warp < BATCH);
    const float2* src = (const float2*)(is_stm ? stm + (size_t)warp * NF
                                               : nstm + (size_t)(warp - BATCH) * NF);
    __half2* dst = (__half2*)(g_F + (size_t)warp * KPAD);

    float cnt = 0.f, ps = 0.f;
    #pragma unroll
    for (int it = 0; it < 3; ++it) {
        int p = lane + it * 32;                      // KPAD/2 = 88 pairs
        if (p < 88) {
            float x = 0.f, y = 0.f;
            if (p < 81) {
                float2 v = src[p];
                x = v.x; y = v.y;
                float2 w = WaccLast[p];
                ps += x * w.x + y * w.y;
                cnt += x + y;
            }
            dst[p] = __floats2half2_rn(x, y);
        }
    }
    #pragma unroll
    for (int o = 16; o; o >>= 1) {
        cnt += __shfl_xor_sync(0xffffffffu, cnt, o);
        ps  += __shfl_xor_sync(0xffffffffu, ps,  o);
    }
    if (lane == 0) {
        if (is_stm) {
            int pc = (int)(cnt + 0.5f);
            int b  = pc / 20;
            b = (b > NB - 1) ? NB - 1 : b;
            int pos = atomicAdd(&g_cnt[b], 1);
            g_perm[b * BATCH + pos] = warp;
            g_psqt_s[warp] = ps;
        } else {
            g_psqt_n[warp - BATCH] = ps;
        }
    }
}

// tile table + pad slots (-1) + re-zero counters for the next replay
__global__ void __launch_bounds__(64) prefix_kernel() {
    __shared__ int scnt[NB], sbase[NB], snt[NB];
    if (threadIdx.x == 0) {
        int t = 0;
        #pragma unroll
        for (int b = 0; b < NB; ++b) {
            scnt[b] = g_cnt[b];
            sbase[b] = t;
            int nt = (scnt[b] + 127) >> 7;
            snt[b] = nt;
            t += nt;
        }
        g_ntiles = t;
    }
    __syncthreads();
    for (int b = 0; b < NB; ++b) {
        for (int i = threadIdx.x; i < snt[b]; i += 64) {
            g_tilebk[sbase[b] + i] = b;
            g_tilem0[sbase[b] + i] = b * BATCH + i * 128;
        }
        for (int i = scnt[b] + threadIdx.x; i < snt[b] * 128; i += 64)
            g_perm[b * BATCH + i] = -1;              // pad slots
    }
    __syncthreads();
    if (threadIdx.x < NB) g_cnt[threadIdx.x] = 0;    // clean state for next launch
}

// ---------------- GEMM1: 512 thr, B-resident, full-tile A double buffer, frag pipeline ----------------
#define BSTR 136
#define ASTR 184
#define G1_SMEM ((KPAD * BSTR + 2 * 128 * ASTR) * 2)

__global__ void __launch_bounds__(512) gemm1_kernel(const float* __restrict__ bias) {
    extern __shared__ __half sh[];
    __half* Bs = sh;                       // [176][BSTR]
    __half* As = sh + KPAD * BSTR;         // [2][128][ASTR]

    const int tid  = threadIdx.x;
    const int lane = tid & 31, wid = tid >> 5;
    const int wm = wid & 3, wn = wid >> 2;          // 4x4 warps, warp tile 32x32
    const int n0 = blockIdx.y * 128;
    const int mslot = blockIdx.x;                   // 0..17

    for (int idx = tid; idx < KPAD * 16; idx += 512) {
        int k = idx >> 4, c = idx & 15;
        asm volatile("cp.async.cg.shared.global [%0], [%1], 16;\n"
                     :: "r"(smem_u32(Bs + k * BSTR + c * 8)),
                        "l"(g_Wt + (size_t)k * ACCN + n0 + c * 8));
    }

    auto loadA = [&](int buf, int mt) {
        const __half* base = g_F + (size_t)mt * 128 * KPAD;
        __half* dst = As + buf * (128 * ASTR);
        #pragma unroll
        for (int it = 0; it < 6; ++it) {
            int idx = tid + it * 512;                // 128 x 22 chunks
            if (idx < 128 * 22) {
                int r = idx / 22, c = idx - r * 22;
                asm volatile("cp.async.cg.shared.global [%0], [%1], 16;\n"
                             :: "r"(smem_u32(dst + r * ASTR + c * 8)),
                                "l"(base + (size_t)r * KPAD + c * 8));
            }
        }
    };

    loadA(0, mslot);
    asm volatile("cp.async.commit_group;\n");
    const int jmax = (512 - mslot + 17) / 18;
    if (jmax > 1) loadA(1, mslot + 18);
    asm volatile("cp.async.commit_group;\n");

    const int g = lane >> 2, t4 = lane & 3;
    int buf = 0;
    for (int j = 0; j < jmax; ++j) {
        const int mt = mslot + j * 18;
        asm volatile("cp.async.wait_group 1;\n");
        __syncthreads();

        float acc[2][4][4];
        #pragma unroll
        for (int i = 0; i < 2; ++i)
            #pragma unroll
            for (int jj = 0; jj < 4; ++jj)
                #pragma unroll
                for (int k = 0; k < 4; ++k) acc[i][jj][k] = 0.f;

        const __half* Ab = As + buf * (128 * ASTR);

        // register fragment double buffer: preload kt+1 while MMA'ing kt
        uint32_t afb[2][2][4], bfb[2][4][2];
        auto ldA = [&](int kt, int s) {
            #pragma unroll
            for (int mf = 0; mf < 2; ++mf) {
                const __half* p = Ab + (wm * 32 + mf * 16 + ((lane >> 3) & 1) * 8 + (lane & 7)) * ASTR
                                     + kt * 16 + (lane >> 4) * 8;
                asm volatile("ldmatrix.sync.aligned.m8n8.x4.shared.b16 {%0,%1,%2,%3}, [%4];\n"
                             : "=r"(afb[s][mf][0]), "=r"(afb[s][mf][1]),
                               "=r"(afb[s][mf][2]), "=r"(afb[s][mf][3])
                             : "r"(smem_u32(p)));
            }
        };
        auto ldB = [&](int kt, int s) {
            #pragma unroll
            for (int ng = 0; ng < 2; ++ng) {
                const __half* p = Bs + (kt * 16 + ((lane >> 3) & 1) * 8 + (lane & 7)) * BSTR
                                     + wn * 32 + ng * 16 + (lane >> 4) * 8;
                uint32_t r0, r1, r2, r3;
                asm volatile("ldmatrix.sync.aligned.m8n8.x4.trans.shared.b16 {%0,%1,%2,%3}, [%4];\n"
                             : "=r"(r0), "=r"(r1), "=r"(r2), "=r"(r3) : "r"(smem_u32(p)));
                bfb[s][ng * 2 + 0][0] = r0; bfb[s][ng * 2 + 0][1] = r1;
                bfb[s][ng * 2 + 1][0] = r2; bfb[s][ng * 2 + 1][1] = r3;
            }
        };

        ldA(0, 0); ldB(0, 0);
        #pragma unroll
        for (int kt = 0; kt < 11; ++kt) {
            const int s = kt & 1;
            if (kt < 10) { ldA(kt + 1, s ^ 1); ldB(kt + 1, s ^ 1); }
            #pragma unroll
            for (int mf = 0; mf < 2; ++mf)
                #pragma unroll
                for (int nf = 0; nf < 4; ++nf)
                    asm volatile(
                        "mma.sync.aligned.m16n8k16.row.col.f32.f16.f16.f32 "
                        "{%0,%1,%2,%3}, {%4,%5,%6,%7}, {%8,%9}, {%0,%1,%2,%3};\n"
                        : "+f"(acc[mf][nf][0]), "+f"(acc[mf][nf][1]),
                          "+f"(acc[mf][nf][2]), "+f"(acc[mf][nf][3])
                        : "r"(afb[s][mf][0]), "r"(afb[s][mf][1]),
                          "r"(afb[s][mf][2]), "r"(afb[s][mf][3]),
                          "r"(bfb[s][nf][0]), "r"(bfb[s][nf][1]));
        }
        __syncthreads();

        if (j + 2 < jmax) loadA(buf, mslot + (j + 2) * 18);
        asm volatile("cp.async.commit_group;\n");

        // epilogue: bias + clip^2 -> g_X
        #pragma unroll
        for (int mf = 0; mf < 2; ++mf) {
            #pragma unroll
            for (int nf = 0; nf < 4; ++nf) {
                const int col = n0 + wn * 32 + nf * 8 + 2 * t4;
                #pragma unroll
                for (int h = 0; h < 2; ++h) {
                    const int row = mt * 128 + wm * 32 + mf * 16 + g + h * 8;
                    float v0 = __saturatef(acc[mf][nf][h * 2 + 0] + bias[col]);     v0 *= v0;
                    float v1 = __saturatef(acc[mf][nf][h * 2 + 1] + bias[col + 1]); v1 *= v1;
                    const size_t off = (row < BATCH)
                        ? (size_t)row * XW + col
                        : (size_t)(row - BATCH) * XW + ACCN + col;
                    *(__half2*)(g_X + off) = __floats2half2_rn(v0, v1);
                }
            }
        }
        buf ^= 1;
    }
}

// ---------------- GEMM2: BK=32, 4-stage ring, 1 sync/iter, overlaid tail ----------------
#define A2STR 40
#define STG_A (128 * A2STR)
#define STG_B (32 * A2STR)
#define STG_H (STG_A + STG_B)
#define NSTG2 4
#define G2_DYN (NSTG2 * STG_H * 2)     // 51200 bytes; overlay (21.3 KB) fits inside

__global__ void __launch_bounds__(256) gemm2_kernel(const float* __restrict__ b1,
                                                    const float* __restrict__ W2,
                                                    const float* __restrict__ b2,
                                                    const float* __restrict__ W3,
                                                    const float* __restrict__ b3,
                                                    float* __restrict__ out) {
    extern __shared__ char dyn[];
    __half* stg = (__half*)dyn;                       // [4][STG_H]
    float* sh1  = (float*)dyn;                        // overlay after main loop
    float* sW2  = sh1 + 128 * 33;
    float* sb2  = sW2 + 1024;
    float* sW3  = sb2 + 32;
    float* sb3p = sW3 + 32;
    __shared__ int sperm[128];

    if (blockIdx.x >= g_ntiles) return;
    const int bk = g_tilebk[blockIdx.x];
    const int m0 = g_tilem0[blockIdx.x];

    const int tid  = threadIdx.x;
    const int lane = tid & 31, wid = tid >> 5;
    const int wm = wid & 3, wn = wid >> 2;            // warp tile 32m x 16n

    if (tid < 128) sperm[tid] = g_perm[m0 + tid];
    __syncthreads();

    const int arow = tid >> 1;
    const int ac2  = (tid & 1) * 2;
    int rp = sperm[arow]; if (rp < 0) rp = 0;
    const __half* gA = g_X + (size_t)rp * XW + ac2 * 8;
    const int brow = tid >> 2, bc = tid & 3;
    const __half* gB = g_W1t + (size_t)brow * 256 + bk * 32 + bc * 8;

    auto issue = [&](int kt) {
        __half* base = stg + (kt & 3) * STG_H;
        uint32_t sa = smem_u32(base + arow * A2STR + ac2 * 8);
        #pragma unroll
        for (int c = 0; c < 2; ++c)
            asm volatile("cp.async.cg.shared.global [%0], [%1], 16;\n"
                         :: "r"(sa + c * 16), "l"(gA + kt * 32 + c * 8));
        if (tid < 128) {
            uint32_t sb = smem_u32(base + STG_A + brow * A2STR + bc * 8);
            asm volatile("cp.async.cg.shared.global [%0], [%1], 16;\n"
                         :: "r"(sb), "l"(gB + (size_t)kt * 32 * 256));
        }
        asm volatile("cp.async.commit_group;\n");
    };

    float acc[2][2][4];
    #pragma unroll
    for (int i = 0; i < 2; ++i)
        #pragma unroll
        for (int j = 0; j < 2; ++j)
            #pragma unroll
            for (int k = 0; k < 4; ++k) acc[i][j][k] = 0.f;

    issue(0); issue(1); issue(2);

    const int KT = XW / 32;   // 64
    for (int kt = 0; kt < KT; ++kt) {
        asm volatile("cp.async.wait_group 2;\n");
        __syncthreads();

        const __half* Ab = stg + (kt & 3) * STG_H;
        const __half* Bb = Ab + STG_A;
        #pragma unroll
        for (int ks = 0; ks < 2; ++ks) {
            uint32_t af[2][4], bf[2][2];
            #pragma unroll
            for (int mf = 0; mf < 2; ++mf) {
                const __half* p = Ab + (wm * 32 + mf * 16 + ((lane >> 3) & 1) * 8 + (lane & 7)) * A2STR
                                     + ks * 16 + (lane >> 4) * 8;
                asm volatile("ldmatrix.sync.aligned.m8n8.x4.shared.b16 {%0,%1,%2,%3}, [%4];\n"
                             : "=r"(af[mf][0]), "=r"(af[mf][1]), "=r"(af[mf][2]), "=r"(af[mf][3])
                             : "r"(smem_u32(p)));
            }
            {
                const __half* p = Bb + (ks * 16 + ((lane >> 3) & 1) * 8 + (lane & 7)) * A2STR
                                     + wn * 16 + (lane >> 4) * 8;
                uint32_t r0, r1, r2, r3;
                asm volatile("ldmatrix.sync.aligned.m8n8.x4.trans.shared.b16 {%0,%1,%2,%3}, [%4];\n"
                             : "=r"(r0), "=r"(r1), "=r"(r2), "=r"(r3) : "r"(smem_u32(p)));
                bf[0][0] = r0; bf[0][1] = r1;
                bf[1][0] = r2; bf[1][1] = r3;
            }
            #pragma unroll
            for (int mf = 0; mf < 2; ++mf)
                #pragma unroll
                for (int nf = 0; nf < 2; ++nf)
                    asm volatile(
                        "mma.sync.aligned.m16n8k16.row.col.f32.f16.f16.f32 "
                        "{%0,%1,%2,%3}, {%4,%5,%6,%7}, {%8,%9}, {%0,%1,%2,%3};\n"
                        : "+f"(acc[mf][nf][0]), "+f"(acc[mf][nf][1]),
                          "+f"(acc[mf][nf][2]), "+f"(acc[mf][nf][3])
                        : "r"(af[mf][0]), "r"(af[mf][1]), "r"(af[mf][2]), "r"(af[mf][3]),
                          "r"(bf[nf][0]), "r"(bf[nf][1]));
        }

        if (kt + 3 < KT) issue(kt + 3);
        else asm volatile("cp.async.commit_group;\n");
    }

    __syncthreads();   // all smem reads done -> overlay is safe

    // epilogue into overlay + load tail weights
    const int g = lane >> 2, t4 = lane & 3;
    #pragma unroll
    for (int mf = 0; mf < 2; ++mf) {
        #pragma unroll
        for (int nf = 0; nf < 2; ++nf) {
            const int col = wn * 16 + nf * 8 + 2 * t4;
            #pragma unroll
            for (int h = 0; h < 2; ++h) {
                const int rl = wm * 32 + mf * 16 + g + h * 8;
                sh1[rl * 33 + col]     = __saturatef(acc[mf][nf][h * 2 + 0] + b1[bk * 32 + col]);
                sh1[rl * 33 + col + 1] = __saturatef(acc[mf][nf][h * 2 + 1] + b1[bk * 32 + col + 1]);
            }
        }
    }
    for (int i = tid; i < 1024; i += 256) sW2[i] = W2[bk * 1024 + i];
    if (tid < 32) { sb2[tid] = b2[bk * 32 + tid]; sW3[tid] = W3[bk * 32 + tid]; }
    if (tid == 0) *sb3p = b3[bk];
    __syncthreads();

    if (tid < 128) {
        const int r = sperm[tid];
        if (r >= 0) {
            const float* hr = &sh1[tid * 33];
            float o = 0.f;
            #pragma unroll 4
            for (int i = 0; i < 32; ++i) {
                float s = sb2[i];
                const float* wr = &sW2[i * 32];
                #pragma unroll
                for (int j = 0; j < 32; ++j) s += wr[j] * hr[j];
                s = __saturatef(s);
                o += sW3[i] * s;
            }
            o += *sb3p + 0.5f * (g_psqt_s[r] - g_psqt_n[r]);
            out[r] = o;
        }
    }
}

// ---------------- launch ----------------
extern "C" void kernel_launch(void* const* d_in, const int* in_sizes, int n_in,
                              void* d_out, int out_size) {
    const float* stm  = (const float*)d_in[0];
    const float* nstm = (const float*)d_in[1];
    const float* Wacc = (const float*)d_in[2];
    const float* bacc = (const float*)d_in[3];
    const float* W1   = (const float*)d_in[4];
    const float* b1   = (const float*)d_in[5];
    const float* W2   = (const float*)d_in[6];
    const float* b2   = (const float*)d_in[7];
    const float* W3   = (const float*)d_in[8];
    const float* b3   = (const float*)d_in[9];
    float* out = (float*)d_out;

    static bool attr_set = false;
    if (!attr_set) {
        cudaFuncSetAttribute(gemm1_kernel, cudaFuncAttributeMaxDynamicSharedMemorySize, G1_SMEM);
        cudaFuncSetAttribute(gemm2_kernel, cudaFuncAttributeMaxDynamicSharedMemorySize, G2_DYN);
        attr_set = true;
    }

    prep_kernel<<<SETUP_BLOCKS + (2 * BATCH) / 8, 256>>>(stm, nstm, Wacc, W1);
    prefix_kernel<<<1, 64>>>();

    dim3 g1(18, ACCN / 128);
    gemm1_kernel<<<g1, 512, G1_SMEM>>>(bacc);

    gemm2_kernel<<<MAXT, 256, G2_DYN>>>(b1, W2, b2, W3, b3, out);
}